// round 9
// baseline (speedup 1.0000x reference)
#include <cuda_runtime.h>
#include <cuda_fp16.h>
#include <cstdint>

#define NROWS 2048
#define KDIM  4096
#define ODIM  4096
#define WELEMS (ODIM * KDIM)       // 16,777,216
#define XELEMS (NROWS * KDIM)      // 8,388,608

// ---------------- scratch (static device globals; no runtime allocation) ----------
__device__ __align__(16) __half g_w_m[WELEMS];
__device__ __align__(16) __half g_w_v[WELEMS];
__device__ __align__(16) __half g_x[XELEMS];
__device__ __align__(16) float g_b_mean[ODIM];
__device__ __align__(16) float g_b_var[ODIM];

// ---------------- helpers ----------------------------------------------------------
__device__ __forceinline__ uint32_t smem_u32(const void* p) {
    uint32_t a;
    asm("{ .reg .u64 t; cvta.to.shared.u64 t, %1; cvt.u32.u64 %0, t; }" : "=r"(a) : "l"(p));
    return a;
}
__device__ __forceinline__ void cp16(uint32_t s, const void* g) {
    asm volatile("cp.async.cg.shared.global [%0], [%1], 16;\n" :: "r"(s), "l"(g));
}
__device__ __forceinline__ void cp_async_arrive(uint32_t mbar) {
    asm volatile("cp.async.mbarrier.arrive.noinc.shared.b64 [%0];" :: "r"(mbar) : "memory");
}
#define MBARRIER_INIT(addr, cnt) \
    asm volatile("mbarrier.init.shared.b64 [%0], %1;" :: "r"((uint32_t)(addr)), "r"((uint32_t)(cnt)) : "memory")
#define MBARRIER_ARRIVE(addr) \
    asm volatile("mbarrier.arrive.shared.b64 _, [%0];" :: "r"((uint32_t)(addr)) : "memory")

#define MBARRIER_WAIT_ACQ(mbar_smem_addr, phase_parity) do { \
    uint32_t _mbar = (uint32_t)(mbar_smem_addr); \
    uint32_t _parity = (uint32_t)(phase_parity); \
    uint32_t _done; \
    asm volatile( \
        "{\n\t.reg .pred p;\n\t" \
        "mbarrier.try_wait.parity.acquire.cta.shared::cta.b64 p, [%1], %2;\n\t" \
        "selp.b32 %0, 1, 0, p;\n\t}" \
        : "=r"(_done) : "r"(_mbar), "r"(_parity) : "memory"); \
    if (!_done) { \
        asm volatile( \
            "{\n\t.reg .pred P1;\n\t" \
            "WAIT_LOOP_%=:\n\t" \
            "mbarrier.try_wait.parity.acquire.cta.shared::cta.b64 P1, [%0], %1, 0x989680;\n\t" \
            "@P1 bra.uni WAIT_DONE_%=;\n\t" \
            "bra.uni WAIT_LOOP_%=;\n\t" \
            "WAIT_DONE_%=:\n\t}" \
            :: "r"(_mbar), "r"(_parity) : "memory"); \
    } \
} while (0)

#define MBARRIER_WAIT_RLX(mbar_smem_addr, phase_parity) do { \
    uint32_t _mbar = (uint32_t)(mbar_smem_addr); \
    uint32_t _parity = (uint32_t)(phase_parity); \
    uint32_t _done; \
    asm volatile( \
        "{\n\t.reg .pred p;\n\t" \
        "mbarrier.try_wait.parity.relaxed.cta.shared::cta.b64 p, [%1], %2, 0x989680;\n\t" \
        "selp.b32 %0, 1, 0, p;\n\t}" \
        : "=r"(_done) : "r"(_mbar), "r"(_parity) : "memory"); \
    if (!_done) { \
        asm volatile( \
            "{\n\t.reg .pred P1;\n\t" \
            "WAIT_LOOP_%=:\n\t" \
            "mbarrier.try_wait.parity.relaxed.cta.shared::cta.b64 P1, [%0], %1, 0x989680;\n\t" \
            "@P1 bra.uni WAIT_DONE_%=;\n\t" \
            "bra.uni WAIT_LOOP_%=;\n\t" \
            "WAIT_DONE_%=:\n\t}" \
            :: "r"(_mbar), "r"(_parity) : "memory"); \
    } \
} while (0)

__device__ __forceinline__ void ldsm4(uint32_t* r, uint32_t addr) {
    asm volatile("ldmatrix.sync.aligned.m8n8.x4.shared.b16 {%0,%1,%2,%3}, [%4];"
                 : "=r"(r[0]), "=r"(r[1]), "=r"(r[2]), "=r"(r[3]) : "r"(addr));
}
__device__ __forceinline__ void mma16816(float* c, const uint32_t* a, const uint32_t* b) {
    asm volatile(
        "mma.sync.aligned.m16n8k16.row.col.f32.f16.f16.f32 "
        "{%0,%1,%2,%3}, {%4,%5,%6,%7}, {%8,%9}, {%0,%1,%2,%3};"
        : "+f"(c[0]), "+f"(c[1]), "+f"(c[2]), "+f"(c[3])
        : "r"(a[0]), "r"(a[1]), "r"(a[2]), "r"(a[3]), "r"(b[0]), "r"(b[1]));
}

// ---------------- prep kernels ----------------------------------------------------
__global__ void __launch_bounds__(256) prep_w_kernel(const float* __restrict__ Wl) {
    size_t i4 = (size_t)blockIdx.x * 256 + threadIdx.x;          // < 4,194,304
    float4 l0 = reinterpret_cast<const float4*>(Wl)[i4];
    float4 l1 = reinterpret_cast<const float4*>(Wl + (size_t)WELEMS)[i4];
    float4 l2 = reinterpret_cast<const float4*>(Wl + 2ull * WELEMS)[i4];
    const float* a0 = reinterpret_cast<const float*>(&l0);
    const float* a1 = reinterpret_cast<const float*>(&l1);
    const float* a2 = reinterpret_cast<const float*>(&l2);
    __half m[4], v[4];
#pragma unroll
    for (int j = 0; j < 4; j++) {
        float e0 = __expf(a0[j]), e1 = __expf(a1[j]), e2 = __expf(a2[j]);
        float inv = __frcp_rn(e0 + e1 + e2);
        float p0 = e0 * inv, p2 = e2 * inv;
        float mean = p2 - p0;
        float var  = (p2 + p0) - mean * mean;
        m[j] = __float2half_rn(mean);
        v[j] = __float2half_rn(var);
    }
    __half2* dm = reinterpret_cast<__half2*>(g_w_m);
    __half2* dv = reinterpret_cast<__half2*>(g_w_v);
    dm[2 * i4]     = __halves2half2(m[0], m[1]);
    dm[2 * i4 + 1] = __halves2half2(m[2], m[3]);
    dv[2 * i4]     = __halves2half2(v[0], v[1]);
    dv[2 * i4 + 1] = __halves2half2(v[2], v[3]);
}

__global__ void __launch_bounds__(256) prep_x_kernel(const float* __restrict__ x) {
    size_t i4 = (size_t)blockIdx.x * 256 + threadIdx.x;          // < 2,097,152
    float4 v = reinterpret_cast<const float4*>(x)[i4];
    const float* a = reinterpret_cast<const float*>(&v);
    __half h[4];
#pragma unroll
    for (int j = 0; j < 4; j++) h[j] = __float2half_rn(a[j]);
    __half2* dh = reinterpret_cast<__half2*>(g_x);
    dh[2 * i4]     = __halves2half2(h[0], h[1]);
    dh[2 * i4 + 1] = __halves2half2(h[2], h[3]);
}

__global__ void __launch_bounds__(256) prep_b_kernel(const float* __restrict__ bl) {
    int o = blockIdx.x * 256 + threadIdx.x;                      // < 4096
    float e0 = __expf(bl[o]);
    float e1 = __expf(bl[ODIM + o]);
    float e2 = __expf(bl[2 * ODIM + o]);
    float inv = __frcp_rn(e0 + e1 + e2);
    float p0 = e0 * inv, p2 = e2 * inv;
    float mean = p2 - p0;
    g_b_mean[o] = mean;
    g_b_var[o]  = (p2 + p0) - mean * mean;
}

// ---------------- GEMM kernel ------------------------------------------------------
// CTA tile: m=128 x o=128, K chunk = 64 fp16. 256 threads (8 warps, 2x4 warp grid,
// warp tile 64m x 32o). 4-stage mbarrier ring, flat 256-step kk pipeline with
// double-buffered B fragments: step j prefetches step j+1's wm/wv ldsm (and the
// once-per-chunk full-wait) so no serial wait->ldsm->mma chain at chunk starts.
// Mean = X*WM ; Var = (X.X)*WV.  mma.sync.m16n8k16 f16 -> fp32.
#define TILE_B      16384                     // 128 rows * 128B (64 fp16)
#define STAGE_B     (3 * TILE_B)              // 49152
#define SM_FULL     0                         // 4 x 8B
#define SM_EMPTY    32                        // 4 x 8B
#define SM_TILES    1024
#define DYN_SMEM    (SM_TILES + 4 * STAGE_B)  // 197632
#define NCHUNK      64
#define NSTEP       (NCHUNK * 4)              // 256

__global__ void __launch_bounds__(256, 1) gemm_kernel(float* __restrict__ out) {
    extern __shared__ char smem[];
    uint32_t sb = smem_u32(smem);
    int tid = threadIdx.x, wid = tid >> 5, lane = tid & 31;
    int warp_m = wid & 1;        // 0..1 -> 64-row half
    int warp_n = wid >> 1;       // 0..3 -> 32-col slice
    int m0 = blockIdx.x * 128;   // m fastest -> concurrent CTAs share w tiles in L2
    int o0 = blockIdx.y * 128;

    if (tid == 0) {
#pragma unroll
        for (int s = 0; s < 4; s++) {
            MBARRIER_INIT(sb + SM_FULL + s * 8, 256);
            MBARRIER_INIT(sb + SM_EMPTY + s * 8, 8);
        }
    }
    __syncthreads();

    const __half* basep[3] = {
        g_x    + (size_t)m0 * KDIM,
        g_w_m  + (size_t)o0 * KDIM,
        g_w_v  + (size_t)o0 * KDIM,
    };

    // ---- cp.async store addressing (per thread, constant) ----
    const int ld_col = tid & 7;          // 16B column
    const int ld_tr  = tid >> 3;         // base row (0..31)
    const uint32_t ld_sw = ((uint32_t)(ld_col * 16)) ^ (((uint32_t)(ld_tr & 7)) << 4);

    auto load_chunk = [&](int chunk, int s) {
        uint32_t sbase = sb + SM_TILES + (uint32_t)s * STAGE_B;
        int k0 = chunk * 64;
#pragma unroll
        for (int t = 0; t < 3; t++) {
            const __half* g = basep[t] + k0 + (size_t)ld_tr * KDIM + ld_col * 8;
            uint32_t tb = sbase + (uint32_t)t * TILE_B + (uint32_t)ld_tr * 128 + ld_sw;
#pragma unroll
            for (int it = 0; it < 4; it++) {
                cp16(tb + it * 32 * 128, g + (size_t)(it * 32) * KDIM);
            }
        }
        cp_async_arrive(sb + SM_FULL + s * 8);   // arrive on full[s] at completion
    };

    // ---- ldmatrix addressing (per lane, constant pieces) ----
    const int a_row = warp_m * 64 + (lane & 15);
    const uint32_t a_rowoff = (uint32_t)a_row * 128;
    const uint32_t a_kb = (uint32_t)((lane >> 4) << 4);
    const uint32_t a_xor = ((uint32_t)(a_row & 7)) << 4;
    const int mi = lane >> 3;
    const int b_row = warp_n * 32 + ((mi & 2) << 2) + (lane & 7);
    const uint32_t b_rowoff = (uint32_t)b_row * 128;
    const uint32_t b_kb = (uint32_t)((mi & 1) << 4);
    const uint32_t b_xor = ((uint32_t)(b_row & 7)) << 4;

    float accm[4][4][4];   // [tm][tn8][4]
    float accv[4][4][4];
#pragma unroll
    for (int i = 0; i < 4; i++)
#pragma unroll
        for (int j = 0; j < 4; j++)
#pragma unroll
            for (int r = 0; r < 4; r++) { accm[i][j][r] = 0.f; accv[i][j][r] = 0.f; }

    // B-fragment ldsm for step (stage s, kk) into regs
    auto ldB = [&](uint32_t* wm, uint32_t* wv, int s, int kk) {
        uint32_t sbase = sb + SM_TILES + (uint32_t)s * STAGE_B;
        uint32_t tWM = sbase + TILE_B;
        uint32_t tWV = sbase + 2 * TILE_B;
        uint32_t bk = ((uint32_t)(kk * 32) + b_kb) ^ b_xor;
#pragma unroll
        for (int tn = 0; tn < 2; tn++) {
            uint32_t ro = b_rowoff + (uint32_t)(tn * 16 * 128) + bk;
            ldsm4(wm + tn * 4, tWM + ro);
            ldsm4(wv + tn * 4, tWV + ro);
        }
    };

    // producer cursor
    int prod_stage = 0, prod_phase = 1;
    // prologue: fill stages 0..2 with chunks 0..2
#pragma unroll
    for (int p = 0; p < 3; p++) {
        MBARRIER_WAIT_RLX(sb + SM_EMPTY + prod_stage * 8, prod_phase);
        load_chunk(p, prod_stage);
        if (++prod_stage == 4) { prod_stage = 0; prod_phase ^= 1; }
    }

    // consumer full-wait cursor (next stage to wait on)
    int cw_stage, cw_phase;

    uint32_t wmA[8], wvA[8], wmB[8], wvB[8];

    // preload step 0
    MBARRIER_WAIT_ACQ(sb + SM_FULL + 0 * 8, 0);
    ldB(wmA, wvA, 0, 0);
    cw_stage = 1; cw_phase = 0;

    for (int j = 0; j < NSTEP; j++) {
        int kkin = j & 3;
        int stage = (j >> 2) & 3;

        // ---- prefetch B frags for step j+1 (and hoisted full-wait at chunk cross) ----
        if (j + 1 < NSTEP) {
            int ns = ((j + 1) >> 2) & 3;
            if (kkin == 3) {
                MBARRIER_WAIT_ACQ(sb + SM_FULL + ns * 8, cw_phase);
                if (++cw_stage == 4) { cw_stage = 0; cw_phase ^= 1; }
            }
            ldB(wmB, wvB, ns, (j + 1) & 3);
        }

        // ---- compute step j using wmA/wvA ----
        {
            uint32_t sbase = sb + SM_TILES + (uint32_t)stage * STAGE_B;
            uint32_t tX = sbase;
            uint32_t ak = ((uint32_t)(kkin * 32) + a_kb) ^ a_xor;
#pragma unroll
            for (int tm = 0; tm < 4; tm++) {
                uint32_t ro = a_rowoff + (uint32_t)(tm * 16 * 128) + ak;
                uint32_t xf[4], xs[4];
                ldsm4(xf, tX + ro);
#pragma unroll
                for (int q = 0; q < 4; q++) {
                    __half2 h = *reinterpret_cast<__half2*>(&xf[q]);
                    h = __hmul2(h, h);
                    xs[q] = *reinterpret_cast<uint32_t*>(&h);
                }
#pragma unroll
                for (int tn8 = 0; tn8 < 4; tn8++) {
                    const uint32_t* bm = &wmA[(tn8 >> 1) * 4 + (tn8 & 1) * 2];
                    const uint32_t* bv = &wvA[(tn8 >> 1) * 4 + (tn8 & 1) * 2];
                    mma16816(accm[tm][tn8], xf, bm);
                    mma16816(accv[tm][tn8], xs, bv);
                }
            }
        }

        // ---- end of chunk: release stage, produce chunk c+3 ----
        if (kkin == 3) {
            if (lane == 0) MBARRIER_ARRIVE(sb + SM_EMPTY + stage * 8);
            int c = j >> 2;
            if (c + 3 < NCHUNK) {
                MBARRIER_WAIT_RLX(sb + SM_EMPTY + prod_stage * 8, prod_phase);
                load_chunk(c + 3, prod_stage);
                if (++prod_stage == 4) { prod_stage = 0; prod_phase ^= 1; }
            }
        }

        // swap B buffers
#pragma unroll
        for (int q = 0; q < 8; q++) {
            uint32_t t = wmA[q]; wmA[q] = wmB[q]; wmB[q] = t;
            t = wvA[q]; wvA[q] = wvB[q]; wvB[q] = t;
        }
    }

    // ---------------- epilogue ----------------
    int ob = o0 + warp_n * 32 + 2 * (lane & 3);
    float2 bm2[4], bv2[4];
#pragma unroll
    for (int tn8 = 0; tn8 < 4; tn8++) {
        bm2[tn8] = *reinterpret_cast<const float2*>(&g_b_mean[ob + tn8 * 8]);
        bv2[tn8] = *reinterpret_cast<const float2*>(&g_b_var[ob + tn8 * 8]);
    }
    int mrow = m0 + warp_m * 64 + (lane >> 2);
#pragma unroll
    for (int tm = 0; tm < 4; tm++) {
        size_t r0 = (size_t)(mrow + tm * 16) * (2 * ODIM);
        size_t r8 = (size_t)(mrow + tm * 16 + 8) * (2 * ODIM);
#pragma unroll
        for (int tn8 = 0; tn8 < 4; tn8++) {
            int oc = ob + tn8 * 8;
            float2 v;
            v.x = accm[tm][tn8][0] + bm2[tn8].x;
            v.y = accm[tm][tn8][1] + bm2[tn8].y;
            *reinterpret_cast<float2*>(out + r0 + oc) = v;
            v.x = accm[tm][tn8][2] + bm2[tn8].x;
            v.y = accm[tm][tn8][3] + bm2[tn8].y;
            *reinterpret_cast<float2*>(out + r8 + oc) = v;
            v.x = accv[tm][tn8][0] + bv2[tn8].x;
            v.y = accv[tm][tn8][1] + bv2[tn8].y;
            *reinterpret_cast<float2*>(out + r0 + ODIM + oc) = v;
            v.x = accv[tm][tn8][2] + bv2[tn8].x;
            v.y = accv[tm][tn8][3] + bv2[tn8].y;
            *reinterpret_cast<float2*>(out + r8 + ODIM + oc) = v;
        }
    }
}

// ---------------- launch -----------------------------------------------------------
extern "C" void kernel_launch(void* const* d_in, const int* in_sizes, int n_in,
                              void* d_out, int out_size) {
    (void)in_sizes; (void)n_in; (void)out_size;
    const float* x  = (const float*)d_in[0];
    const float* Wl = (const float*)d_in[1];
    const float* bl = (const float*)d_in[2];
    float* out = (float*)d_out;

    prep_w_kernel<<<WELEMS / 4 / 256, 256>>>(Wl);   // 16384 blocks
    prep_x_kernel<<<XELEMS / 4 / 256, 256>>>(x);    // 8192 blocks
    prep_b_kernel<<<ODIM / 256, 256>>>(bl);         // 16 blocks

    cudaFuncSetAttribute(gemm_kernel, cudaFuncAttributeMaxDynamicSharedMemorySize, DYN_SMEM);
    gemm_kernel<<<dim3(NROWS / 128, ODIM / 128, 1), 256, DYN_SMEM>>>(out);
}

// round 10
// speedup vs baseline: 1.3758x; 1.3758x over previous
#include <cuda_runtime.h>
#include <cuda_fp16.h>
#include <cstdint>

#define NROWS 2048
#define KDIM  4096
#define ODIM  4096
#define WELEMS (ODIM * KDIM)       // 16,777,216
#define XELEMS (NROWS * KDIM)      // 8,388,608

// ---------------- scratch (static device globals; no runtime allocation) ----------
__device__ __align__(16) __half g_w_m[WELEMS];
__device__ __align__(16) __half g_w_v[WELEMS];
__device__ __align__(16) __half g_x[XELEMS];
__device__ __align__(16) float g_b_mean[ODIM];
__device__ __align__(16) float g_b_var[ODIM];

// ---------------- helpers ----------------------------------------------------------
__device__ __forceinline__ uint32_t smem_u32(const void* p) {
    uint32_t a;
    asm("{ .reg .u64 t; cvta.to.shared.u64 t, %1; cvt.u32.u64 %0, t; }" : "=r"(a) : "l"(p));
    return a;
}
__device__ __forceinline__ void cp16(uint32_t s, const void* g) {
    asm volatile("cp.async.cg.shared.global [%0], [%1], 16;\n" :: "r"(s), "l"(g));
}
__device__ __forceinline__ void cp_async_arrive(uint32_t mbar) {
    asm volatile("cp.async.mbarrier.arrive.noinc.shared.b64 [%0];" :: "r"(mbar) : "memory");
}
__device__ __forceinline__ void red_add_f32(float* p, float v) {
    asm volatile("red.global.add.f32 [%0], %1;" :: "l"(p), "f"(v) : "memory");
}
#define MBARRIER_INIT(addr, cnt) \
    asm volatile("mbarrier.init.shared.b64 [%0], %1;" :: "r"((uint32_t)(addr)), "r"((uint32_t)(cnt)) : "memory")
#define MBARRIER_ARRIVE(addr) \
    asm volatile("mbarrier.arrive.shared.b64 _, [%0];" :: "r"((uint32_t)(addr)) : "memory")

#define MBARRIER_WAIT_ACQ(mbar_smem_addr, phase_parity) do { \
    uint32_t _mbar = (uint32_t)(mbar_smem_addr); \
    uint32_t _parity = (uint32_t)(phase_parity); \
    uint32_t _done; \
    asm volatile( \
        "{\n\t.reg .pred p;\n\t" \
        "mbarrier.try_wait.parity.acquire.cta.shared::cta.b64 p, [%1], %2;\n\t" \
        "selp.b32 %0, 1, 0, p;\n\t}" \
        : "=r"(_done) : "r"(_mbar), "r"(_parity) : "memory"); \
    if (!_done) { \
        asm volatile( \
            "{\n\t.reg .pred P1;\n\t" \
            "WAIT_LOOP_%=:\n\t" \
            "mbarrier.try_wait.parity.acquire.cta.shared::cta.b64 P1, [%0], %1, 0x989680;\n\t" \
            "@P1 bra.uni WAIT_DONE_%=;\n\t" \
            "bra.uni WAIT_LOOP_%=;\n\t" \
            "WAIT_DONE_%=:\n\t}" \
            :: "r"(_mbar), "r"(_parity) : "memory"); \
    } \
} while (0)

#define MBARRIER_WAIT_RLX(mbar_smem_addr, phase_parity) do { \
    uint32_t _mbar = (uint32_t)(mbar_smem_addr); \
    uint32_t _parity = (uint32_t)(phase_parity); \
    uint32_t _done; \
    asm volatile( \
        "{\n\t.reg .pred p;\n\t" \
        "mbarrier.try_wait.parity.relaxed.cta.shared::cta.b64 p, [%1], %2, 0x989680;\n\t" \
        "selp.b32 %0, 1, 0, p;\n\t}" \
        : "=r"(_done) : "r"(_mbar), "r"(_parity) : "memory"); \
    if (!_done) { \
        asm volatile( \
            "{\n\t.reg .pred P1;\n\t" \
            "WAIT_LOOP_%=:\n\t" \
            "mbarrier.try_wait.parity.relaxed.cta.shared::cta.b64 P1, [%0], %1, 0x989680;\n\t" \
            "@P1 bra.uni WAIT_DONE_%=;\n\t" \
            "bra.uni WAIT_LOOP_%=;\n\t" \
            "WAIT_DONE_%=:\n\t}" \
            :: "r"(_mbar), "r"(_parity) : "memory"); \
    } \
} while (0)

__device__ __forceinline__ void ldsm4(uint32_t* r, uint32_t addr) {
    asm volatile("ldmatrix.sync.aligned.m8n8.x4.shared.b16 {%0,%1,%2,%3}, [%4];"
                 : "=r"(r[0]), "=r"(r[1]), "=r"(r[2]), "=r"(r[3]) : "r"(addr));
}
__device__ __forceinline__ void mma16816(float* c, const uint32_t* a, const uint32_t* b) {
    asm volatile(
        "mma.sync.aligned.m16n8k16.row.col.f32.f16.f16.f32 "
        "{%0,%1,%2,%3}, {%4,%5,%6,%7}, {%8,%9}, {%0,%1,%2,%3};"
        : "+f"(c[0]), "+f"(c[1]), "+f"(c[2]), "+f"(c[3])
        : "r"(a[0]), "r"(a[1]), "r"(a[2]), "r"(a[3]), "r"(b[0]), "r"(b[1]));
}

// ---------------- prep kernels ----------------------------------------------------
__global__ void __launch_bounds__(256) prep_w_kernel(const float* __restrict__ Wl) {
    size_t i4 = (size_t)blockIdx.x * 256 + threadIdx.x;          // < 4,194,304
    float4 l0 = reinterpret_cast<const float4*>(Wl)[i4];
    float4 l1 = reinterpret_cast<const float4*>(Wl + (size_t)WELEMS)[i4];
    float4 l2 = reinterpret_cast<const float4*>(Wl + 2ull * WELEMS)[i4];
    const float* a0 = reinterpret_cast<const float*>(&l0);
    const float* a1 = reinterpret_cast<const float*>(&l1);
    const float* a2 = reinterpret_cast<const float*>(&l2);
    __half m[4], v[4];
#pragma unroll
    for (int j = 0; j < 4; j++) {
        float e0 = __expf(a0[j]), e1 = __expf(a1[j]), e2 = __expf(a2[j]);
        float inv = __frcp_rn(e0 + e1 + e2);
        float p0 = e0 * inv, p2 = e2 * inv;
        float mean = p2 - p0;
        float var  = (p2 + p0) - mean * mean;
        m[j] = __float2half_rn(mean);
        v[j] = __float2half_rn(var);
    }
    __half2* dm = reinterpret_cast<__half2*>(g_w_m);
    __half2* dv = reinterpret_cast<__half2*>(g_w_v);
    dm[2 * i4]     = __halves2half2(m[0], m[1]);
    dm[2 * i4 + 1] = __halves2half2(m[2], m[3]);
    dv[2 * i4]     = __halves2half2(v[0], v[1]);
    dv[2 * i4 + 1] = __halves2half2(v[2], v[3]);
}

__global__ void __launch_bounds__(256) prep_x_kernel(const float* __restrict__ x) {
    size_t i4 = (size_t)blockIdx.x * 256 + threadIdx.x;          // < 2,097,152
    float4 v = reinterpret_cast<const float4*>(x)[i4];
    const float* a = reinterpret_cast<const float*>(&v);
    __half h[4];
#pragma unroll
    for (int j = 0; j < 4; j++) h[j] = __float2half_rn(a[j]);
    __half2* dh = reinterpret_cast<__half2*>(g_x);
    dh[2 * i4]     = __halves2half2(h[0], h[1]);
    dh[2 * i4 + 1] = __halves2half2(h[2], h[3]);
}

__global__ void __launch_bounds__(256) prep_b_kernel(const float* __restrict__ bl) {
    int o = blockIdx.x * 256 + threadIdx.x;                      // < 4096
    float e0 = __expf(bl[o]);
    float e1 = __expf(bl[ODIM + o]);
    float e2 = __expf(bl[2 * ODIM + o]);
    float inv = __frcp_rn(e0 + e1 + e2);
    float p0 = e0 * inv, p2 = e2 * inv;
    float mean = p2 - p0;
    g_b_mean[o] = mean;
    g_b_var[o]  = (p2 + p0) - mean * mean;
}

// Fill out with bias moments: out[n,0,o] = b_mean[o], out[n,1,o] = b_var[o].
// GEMM splits then red.add their partial sums on top.
__global__ void __launch_bounds__(256) fill_out_kernel(float* __restrict__ out) {
    size_t t4 = (size_t)blockIdx.x * 256 + threadIdx.x;          // < 4,194,304 float4s
    int half = (int)((t4 >> 10) & 1);
    int o4 = (int)(t4 & 1023);
    const float4* src = reinterpret_cast<const float4*>(half ? g_b_var : g_b_mean);
    reinterpret_cast<float4*>(out)[t4] = src[o4];
}

// ---------------- GEMM kernel ------------------------------------------------------
// Split-K=2: grid (16, 32, 2); CTA tile m=128 x o=128 x K=2048 (32 chunks of 64).
// 256 threads (8 warps, 2x4 grid, warp tile 64m x 32o). 4-stage mbarrier ring
// (R6 structure). Epilogue: red.global.add.f32 onto bias-prefilled out.
// Mean = X*WM ; Var = (X.X)*WV.  mma.sync.m16n8k16 f16 -> fp32.
#define TILE_B      16384                     // 128 rows * 128B (64 fp16)
#define STAGE_B     (3 * TILE_B)              // 49152
#define SM_FULL     0                         // 4 x 8B
#define SM_EMPTY    32                        // 4 x 8B
#define SM_TILES    1024
#define DYN_SMEM    (SM_TILES + 4 * STAGE_B)  // 197632
#define NCHUNK      32                        // 2048 K per split

__global__ void __launch_bounds__(256, 1) gemm_kernel(float* __restrict__ out) {
    extern __shared__ char smem[];
    uint32_t sb = smem_u32(smem);
    int tid = threadIdx.x, wid = tid >> 5, lane = tid & 31;
    int warp_m = wid & 1;        // 0..1 -> 64-row half
    int warp_n = wid >> 1;       // 0..3 -> 32-col slice
    int m0 = blockIdx.x * 128;   // m fastest -> concurrent CTAs share w tiles in L2
    int o0 = blockIdx.y * 128;
    int k0base = blockIdx.z * (NCHUNK * 64);   // split-K offset

    if (tid == 0) {
#pragma unroll
        for (int s = 0; s < 4; s++) {
            MBARRIER_INIT(sb + SM_FULL + s * 8, 256);
            MBARRIER_INIT(sb + SM_EMPTY + s * 8, 8);
        }
    }
    __syncthreads();

    const __half* basep[3] = {
        g_x    + (size_t)m0 * KDIM + k0base,
        g_w_m  + (size_t)o0 * KDIM + k0base,
        g_w_v  + (size_t)o0 * KDIM + k0base,
    };

    // ---- cp.async store addressing (per thread, constant) ----
    const int ld_col = tid & 7;          // 16B column
    const int ld_tr  = tid >> 3;         // base row (0..31)
    const uint32_t ld_sw = ((uint32_t)(ld_col * 16)) ^ (((uint32_t)(ld_tr & 7)) << 4);

    auto load_chunk = [&](int chunk, int s) {
        uint32_t sbase = sb + SM_TILES + (uint32_t)s * STAGE_B;
        int k0 = chunk * 64;
#pragma unroll
        for (int t = 0; t < 3; t++) {
            const __half* g = basep[t] + k0 + (size_t)ld_tr * KDIM + ld_col * 8;
            uint32_t tb = sbase + (uint32_t)t * TILE_B + (uint32_t)ld_tr * 128 + ld_sw;
#pragma unroll
            for (int it = 0; it < 4; it++) {
                cp16(tb + it * 32 * 128, g + (size_t)(it * 32) * KDIM);
            }
        }
        cp_async_arrive(sb + SM_FULL + s * 8);   // arrive on full[s] at completion
    };

    // ---- ldmatrix addressing (per lane, constant pieces) ----
    const int a_row = warp_m * 64 + (lane & 15);
    const uint32_t a_rowoff = (uint32_t)a_row * 128;
    const uint32_t a_kb = (uint32_t)((lane >> 4) << 4);
    const uint32_t a_xor = ((uint32_t)(a_row & 7)) << 4;
    const int mi = lane >> 3;
    const int b_row = warp_n * 32 + ((mi & 2) << 2) + (lane & 7);
    const uint32_t b_rowoff = (uint32_t)b_row * 128;
    const uint32_t b_kb = (uint32_t)((mi & 1) << 4);
    const uint32_t b_xor = ((uint32_t)(b_row & 7)) << 4;

    float accm[4][4][4];   // [tm][tn8][4]
    float accv[4][4][4];
#pragma unroll
    for (int i = 0; i < 4; i++)
#pragma unroll
        for (int j = 0; j < 4; j++)
#pragma unroll
            for (int r = 0; r < 4; r++) { accm[i][j][r] = 0.f; accv[i][j][r] = 0.f; }

    // producer cursor: starts stage 0 / phase 1 (first waits pass immediately)
    int prod_stage = 0, prod_phase = 1;
    // consumer cursor: starts stage 0 / phase 0
    int cons_stage = 0, cons_phase = 0;

    // prologue: fill stages 0..2 with chunks 0..2
#pragma unroll
    for (int p = 0; p < 3; p++) {
        MBARRIER_WAIT_RLX(sb + SM_EMPTY + prod_stage * 8, prod_phase);
        load_chunk(p, prod_stage);
        if (++prod_stage == 4) { prod_stage = 0; prod_phase ^= 1; }
    }

    for (int i = 0; i < NCHUNK; i++) {
        // ---- consume chunk i ----
        MBARRIER_WAIT_ACQ(sb + SM_FULL + cons_stage * 8, cons_phase);

        uint32_t sbase = sb + SM_TILES + (uint32_t)cons_stage * STAGE_B;
        uint32_t tX  = sbase;
        uint32_t tWM = sbase + TILE_B;
        uint32_t tWV = sbase + 2 * TILE_B;

#pragma unroll
        for (int kk = 0; kk < 4; kk++) {
            uint32_t ak = ((uint32_t)(kk * 32) + a_kb) ^ a_xor;
            uint32_t bk = ((uint32_t)(kk * 32) + b_kb) ^ b_xor;
            uint32_t wm[8], wv[8];
#pragma unroll
            for (int tn = 0; tn < 2; tn++) {
                uint32_t ro = b_rowoff + (uint32_t)(tn * 16 * 128) + bk;
                ldsm4(wm + tn * 4, tWM + ro);
                ldsm4(wv + tn * 4, tWV + ro);
            }
#pragma unroll
            for (int tm = 0; tm < 4; tm++) {
                uint32_t ro = a_rowoff + (uint32_t)(tm * 16 * 128) + ak;
                uint32_t xf[4], xs[4];
                ldsm4(xf, tX + ro);
#pragma unroll
                for (int j = 0; j < 4; j++) {
                    __half2 h = *reinterpret_cast<__half2*>(&xf[j]);
                    h = __hmul2(h, h);
                    xs[j] = *reinterpret_cast<uint32_t*>(&h);
                }
#pragma unroll
                for (int tn8 = 0; tn8 < 4; tn8++) {
                    const uint32_t* bm = &wm[(tn8 >> 1) * 4 + (tn8 & 1) * 2];
                    const uint32_t* bv = &wv[(tn8 >> 1) * 4 + (tn8 & 1) * 2];
                    mma16816(accm[tm][tn8], xf, bm);
                    mma16816(accv[tm][tn8], xs, bv);
                }
            }
        }

        // this warp is done reading stage cons_stage
        if (lane == 0) MBARRIER_ARRIVE(sb + SM_EMPTY + cons_stage * 8);
        if (++cons_stage == 4) { cons_stage = 0; cons_phase ^= 1; }

        // ---- produce chunk i+3 ----
        if (i + 3 < NCHUNK) {
            MBARRIER_WAIT_RLX(sb + SM_EMPTY + prod_stage * 8, prod_phase);
            load_chunk(i + 3, prod_stage);
            if (++prod_stage == 4) { prod_stage = 0; prod_phase ^= 1; }
        }
    }

    // ---------------- epilogue: red.add partials onto bias-prefilled out -----------
    int ob = o0 + warp_n * 32 + 2 * (lane & 3);
    int mrow = m0 + warp_m * 64 + (lane >> 2);
#pragma unroll
    for (int tm = 0; tm < 4; tm++) {
        size_t r0 = (size_t)(mrow + tm * 16) * (2 * ODIM);
        size_t r8 = (size_t)(mrow + tm * 16 + 8) * (2 * ODIM);
#pragma unroll
        for (int tn8 = 0; tn8 < 4; tn8++) {
            int oc = ob + tn8 * 8;
            red_add_f32(out + r0 + oc,            accm[tm][tn8][0]);
            red_add_f32(out + r0 + oc + 1,        accm[tm][tn8][1]);
            red_add_f32(out + r8 + oc,            accm[tm][tn8][2]);
            red_add_f32(out + r8 + oc + 1,        accm[tm][tn8][3]);
            red_add_f32(out + r0 + ODIM + oc,     accv[tm][tn8][0]);
            red_add_f32(out + r0 + ODIM + oc + 1, accv[tm][tn8][1]);
            red_add_f32(out + r8 + ODIM + oc,     accv[tm][tn8][2]);
            red_add_f32(out + r8 + ODIM + oc + 1, accv[tm][tn8][3]);
        }
    }
}

// ---------------- launch -----------------------------------------------------------
extern "C" void kernel_launch(void* const* d_in, const int* in_sizes, int n_in,
                              void* d_out, int out_size) {
    (void)in_sizes; (void)n_in; (void)out_size;
    const float* x  = (const float*)d_in[0];
    const float* Wl = (const float*)d_in[1];
    const float* bl = (const float*)d_in[2];
    float* out = (float*)d_out;

    prep_w_kernel<<<WELEMS / 4 / 256, 256>>>(Wl);   // 16384 blocks
    prep_x_kernel<<<XELEMS / 4 / 256, 256>>>(x);    // 8192 blocks
    prep_b_kernel<<<ODIM / 256, 256>>>(bl);         // 16 blocks
    fill_out_kernel<<<(NROWS * 2 * ODIM / 4) / 256, 256>>>(out);  // 16384 blocks

    cudaFuncSetAttribute(gemm_kernel, cudaFuncAttributeMaxDynamicSharedMemorySize, DYN_SMEM);
    gemm_kernel<<<dim3(NROWS / 128, ODIM / 128, 2), 256, DYN_SMEM>>>(out);
}

// round 14
// speedup vs baseline: 1.3917x; 1.0116x over previous
#include <cuda_runtime.h>
#include <cuda_fp16.h>
#include <cstdint>

#define NROWS 2048
#define KDIM  4096
#define ODIM  4096
#define WELEMS (ODIM * KDIM)       // 16,777,216
#define XELEMS (NROWS * KDIM)      // 8,388,608

// ---------------- scratch (static device globals; no runtime allocation) ----------
__device__ __align__(16) __half g_w_m[WELEMS];
__device__ __align__(16) __half g_w_v[WELEMS];
__device__ __align__(16) __half g_x[XELEMS];
__device__ __align__(16) float g_b_mean[ODIM];
__device__ __align__(16) float g_b_var[ODIM];

// ---------------- helpers ----------------------------------------------------------
__device__ __forceinline__ uint32_t smem_u32(const void* p) {
    uint32_t a;
    asm("{ .reg .u64 t; cvta.to.shared.u64 t, %1; cvt.u32.u64 %0, t; }" : "=r"(a) : "l"(p));
    return a;
}
__device__ __forceinline__ void cp16(uint32_t s, const void* g) {
    asm volatile("cp.async.cg.shared.global [%0], [%1], 16;\n" :: "r"(s), "l"(g));
}
__device__ __forceinline__ void cp_async_arrive(uint32_t mbar) {
    asm volatile("cp.async.mbarrier.arrive.noinc.shared.b64 [%0];" :: "r"(mbar) : "memory");
}
#define MBARRIER_INIT(addr, cnt) \
    asm volatile("mbarrier.init.shared.b64 [%0], %1;" :: "r"((uint32_t)(addr)), "r"((uint32_t)(cnt)) : "memory")
#define MBARRIER_ARRIVE(addr) \
    asm volatile("mbarrier.arrive.shared.b64 _, [%0];" :: "r"((uint32_t)(addr)) : "memory")

#define MBARRIER_WAIT_ACQ(mbar_smem_addr, phase_parity) do { \
    uint32_t _mbar = (uint32_t)(mbar_smem_addr); \
    uint32_t _parity = (uint32_t)(phase_parity); \
    uint32_t _done; \
    asm volatile( \
        "{\n\t.reg .pred p;\n\t" \
        "mbarrier.try_wait.parity.acquire.cta.shared::cta.b64 p, [%1], %2;\n\t" \
        "selp.b32 %0, 1, 0, p;\n\t}" \
        : "=r"(_done) : "r"(_mbar), "r"(_parity) : "memory"); \
    if (!_done) { \
        asm volatile( \
            "{\n\t.reg .pred P1;\n\t" \
            "WAIT_LOOP_%=:\n\t" \
            "mbarrier.try_wait.parity.acquire.cta.shared::cta.b64 P1, [%0], %1, 0x989680;\n\t" \
            "@P1 bra.uni WAIT_DONE_%=;\n\t" \
            "bra.uni WAIT_LOOP_%=;\n\t" \
            "WAIT_DONE_%=:\n\t}" \
            :: "r"(_mbar), "r"(_parity) : "memory"); \
    } \
} while (0)

#define MBARRIER_WAIT_RLX(mbar_smem_addr, phase_parity) do { \
    uint32_t _mbar = (uint32_t)(mbar_smem_addr); \
    uint32_t _parity = (uint32_t)(phase_parity); \
    uint32_t _done; \
    asm volatile( \
        "{\n\t.reg .pred p;\n\t" \
        "mbarrier.try_wait.parity.relaxed.cta.shared::cta.b64 p, [%1], %2, 0x989680;\n\t" \
        "selp.b32 %0, 1, 0, p;\n\t}" \
        : "=r"(_done) : "r"(_mbar), "r"(_parity) : "memory"); \
    if (!_done) { \
        asm volatile( \
            "{\n\t.reg .pred P1;\n\t" \
            "WAIT_LOOP_%=:\n\t" \
            "mbarrier.try_wait.parity.relaxed.cta.shared::cta.b64 P1, [%0], %1, 0x989680;\n\t" \
            "@P1 bra.uni WAIT_DONE_%=;\n\t" \
            "bra.uni WAIT_LOOP_%=;\n\t" \
            "WAIT_DONE_%=:\n\t}" \
            :: "r"(_mbar), "r"(_parity) : "memory"); \
    } \
} while (0)

__device__ __forceinline__ void ldsm4(uint32_t* r, uint32_t addr) {
    asm volatile("ldmatrix.sync.aligned.m8n8.x4.shared.b16 {%0,%1,%2,%3}, [%4];"
                 : "=r"(r[0]), "=r"(r[1]), "=r"(r[2]), "=r"(r[3]) : "r"(addr));
}
__device__ __forceinline__ void mma16816(float* c, const uint32_t* a, const uint32_t* b) {
    asm volatile(
        "mma.sync.aligned.m16n8k16.row.col.f32.f16.f16.f32 "
        "{%0,%1,%2,%3}, {%4,%5,%6,%7}, {%8,%9}, {%0,%1,%2,%3};"
        : "+f"(c[0]), "+f"(c[1]), "+f"(c[2]), "+f"(c[3])
        : "r"(a[0]), "r"(a[1]), "r"(a[2]), "r"(a[3]), "r"(b[0]), "r"(b[1]));
}

// ---------------- prep kernels ----------------------------------------------------
__global__ void __launch_bounds__(256) prep_w_kernel(const float* __restrict__ Wl) {
    size_t i4 = (size_t)blockIdx.x * 256 + threadIdx.x;          // < 4,194,304
    float4 l0 = reinterpret_cast<const float4*>(Wl)[i4];
    float4 l1 = reinterpret_cast<const float4*>(Wl + (size_t)WELEMS)[i4];
    float4 l2 = reinterpret_cast<const float4*>(Wl + 2ull * WELEMS)[i4];
    const float* a0 = reinterpret_cast<const float*>(&l0);
    const float* a1 = reinterpret_cast<const float*>(&l1);
    const float* a2 = reinterpret_cast<const float*>(&l2);
    __half m[4], v[4];
#pragma unroll
    for (int j = 0; j < 4; j++) {
        float e0 = __expf(a0[j]), e1 = __expf(a1[j]), e2 = __expf(a2[j]);
        float inv = __frcp_rn(e0 + e1 + e2);
        float p0 = e0 * inv, p2 = e2 * inv;
        float mean = p2 - p0;
        float var  = (p2 + p0) - mean * mean;
        m[j] = __float2half_rn(mean);
        v[j] = __float2half_rn(var);
    }
    __half2* dm = reinterpret_cast<__half2*>(g_w_m);
    __half2* dv = reinterpret_cast<__half2*>(g_w_v);
    dm[2 * i4]     = __halves2half2(m[0], m[1]);
    dm[2 * i4 + 1] = __halves2half2(m[2], m[3]);
    dv[2 * i4]     = __halves2half2(v[0], v[1]);
    dv[2 * i4 + 1] = __halves2half2(v[2], v[3]);
}

__global__ void __launch_bounds__(256) prep_x_kernel(const float* __restrict__ x) {
    size_t i4 = (size_t)blockIdx.x * 256 + threadIdx.x;          // < 2,097,152
    float4 v = reinterpret_cast<const float4*>(x)[i4];
    const float* a = reinterpret_cast<const float*>(&v);
    __half h[4];
#pragma unroll
    for (int j = 0; j < 4; j++) h[j] = __float2half_rn(a[j]);
    __half2* dh = reinterpret_cast<__half2*>(g_x);
    dh[2 * i4]     = __halves2half2(h[0], h[1]);
    dh[2 * i4 + 1] = __halves2half2(h[2], h[3]);
}

__global__ void __launch_bounds__(256) prep_b_kernel(const float* __restrict__ bl) {
    int o = blockIdx.x * 256 + threadIdx.x;                      // < 4096
    float e0 = __expf(bl[o]);
    float e1 = __expf(bl[ODIM + o]);
    float e2 = __expf(bl[2 * ODIM + o]);
    float inv = __frcp_rn(e0 + e1 + e2);
    float p0 = e0 * inv, p2 = e2 * inv;
    float mean = p2 - p0;
    g_b_mean[o] = mean;
    g_b_var[o]  = (p2 + p0) - mean * mean;
}

// ---------------- GEMM kernel ------------------------------------------------------
// CTA tile: m=128 x o=128, K chunk = 64 fp16. 256 threads (8 warps, 2x4 warp grid,
// warp tile 64m x 32o). 4-stage mbarrier ring (R6 structure). NEW: odd warps
// traverse the kk sequence rotated by 2 (2,3,0,1) so the two warps per SMSP are
// in opposite ldsm/mma phases -> SMEM crossbar bursts overlap tensor bursts.
// Mean = X*WM ; Var = (X.X)*WV.  mma.sync.m16n8k16 f16 -> fp32.
#define TILE_B      16384                     // 128 rows * 128B (64 fp16)
#define STAGE_B     (3 * TILE_B)              // 49152
#define SM_FULL     0                         // 4 x 8B
#define SM_EMPTY    32                        // 4 x 8B
#define SM_TILES    1024
#define DYN_SMEM    (SM_TILES + 4 * STAGE_B)  // 197632
#define NCHUNK      64

__global__ void __launch_bounds__(256, 1) gemm_kernel(float* __restrict__ out) {
    extern __shared__ char smem[];
    uint32_t sb = smem_u32(smem);
    int tid = threadIdx.x, wid = tid >> 5, lane = tid & 31;
    int warp_m = wid & 1;        // 0..1 -> 64-row half
    int warp_n = wid >> 1;       // 0..3 -> 32-col slice
    int m0 = blockIdx.x * 128;   // m fastest -> concurrent CTAs share w tiles in L2
    int o0 = blockIdx.y * 128;

    if (tid == 0) {
#pragma unroll
        for (int s = 0; s < 4; s++) {
            MBARRIER_INIT(sb + SM_FULL + s * 8, 256);
            MBARRIER_INIT(sb + SM_EMPTY + s * 8, 8);
        }
    }
    __syncthreads();

    const __half* basep[3] = {
        g_x    + (size_t)m0 * KDIM,
        g_w_m  + (size_t)o0 * KDIM,
        g_w_v  + (size_t)o0 * KDIM,
    };

    // ---- cp.async store addressing (per thread, constant) ----
    const int ld_col = tid & 7;          // 16B column
    const int ld_tr  = tid >> 3;         // base row (0..31)
    const uint32_t ld_sw = ((uint32_t)(ld_col * 16)) ^ (((uint32_t)(ld_tr & 7)) << 4);

    auto load_chunk = [&](int chunk, int s) {
        uint32_t sbase = sb + SM_TILES + (uint32_t)s * STAGE_B;
        int k0 = chunk * 64;
#pragma unroll
        for (int t = 0; t < 3; t++) {
            const __half* g = basep[t] + k0 + (size_t)ld_tr * KDIM + ld_col * 8;
            uint32_t tb = sbase + (uint32_t)t * TILE_B + (uint32_t)ld_tr * 128 + ld_sw;
#pragma unroll
            for (int it = 0; it < 4; it++) {
                cp16(tb + it * 32 * 128, g + (size_t)(it * 32) * KDIM);
            }
        }
        cp_async_arrive(sb + SM_FULL + s * 8);   // arrive on full[s] at completion
    };

    // ---- ldmatrix addressing (per lane, constant pieces) ----
    const int a_row = warp_m * 64 + (lane & 15);
    const uint32_t a_rowoff = (uint32_t)a_row * 128;
    const uint32_t a_kb = (uint32_t)((lane >> 4) << 4);
    const uint32_t a_xor = ((uint32_t)(a_row & 7)) << 4;
    const int mi = lane >> 3;
    const int b_row = warp_n * 32 + ((mi & 2) << 2) + (lane & 7);
    const uint32_t b_rowoff = (uint32_t)b_row * 128;
    const uint32_t b_kb = (uint32_t)((mi & 1) << 4);
    const uint32_t b_xor = ((uint32_t)(b_row & 7)) << 4;

    float accm[4][4][4];   // [tm][tn8][4]
    float accv[4][4][4];
#pragma unroll
    for (int i = 0; i < 4; i++)
#pragma unroll
        for (int j = 0; j < 4; j++)
#pragma unroll
            for (int r = 0; r < 4; r++) { accm[i][j][r] = 0.f; accv[i][j][r] = 0.f; }

    // producer cursor: starts stage 0 / phase 1 (first waits pass immediately)
    int prod_stage = 0, prod_phase = 1;
    // consumer cursor: starts stage 0 / phase 0
    int cons_stage = 0, cons_phase = 0;

    // prologue: fill stages 0..2 with chunks 0..2
#pragma unroll
    for (int p = 0; p < 3; p++) {
        MBARRIER_WAIT_RLX(sb + SM_EMPTY + prod_stage * 8, prod_phase);
        load_chunk(p, prod_stage);
        if (++prod_stage == 4) { prod_stage = 0; prod_phase ^= 1; }
    }

    const bool rot = (wid & 1) != 0;   // odd warps: kk order 2,3,0,1

    for (int i = 0; i < NCHUNK; i++) {
        // ---- consume chunk i ----
        MBARRIER_WAIT_ACQ(sb + SM_FULL + cons_stage * 8, cons_phase);

        uint32_t sbase = sb + SM_TILES + (uint32_t)cons_stage * STAGE_B;
        uint32_t tX  = sbase;
        uint32_t tWM = sbase + TILE_B;
        uint32_t tWV = sbase + 2 * TILE_B;

        auto do_kk = [&](int kk) {
            uint32_t ak = ((uint32_t)(kk * 32) + a_kb) ^ a_xor;
            uint32_t bk = ((uint32_t)(kk * 32) + b_kb) ^ b_xor;
            uint32_t wm[8], wv[8];
#pragma unroll
            for (int tn = 0; tn < 2; tn++) {
                uint32_t ro = b_rowoff + (uint32_t)(tn * 16 * 128) + bk;
                ldsm4(wm + tn * 4, tWM + ro);
                ldsm4(wv + tn * 4, tWV + ro);
            }
#pragma unroll
            for (int tm = 0; tm < 4; tm++) {
                uint32_t ro = a_rowoff + (uint32_t)(tm * 16 * 128) + ak;
                uint32_t xf[4], xs[4];
                ldsm4(xf, tX + ro);
#pragma unroll
                for (int j = 0; j < 4; j++) {
                    __half2 h = *reinterpret_cast<__half2*>(&xf[j]);
                    h = __hmul2(h, h);
                    xs[j] = *reinterpret_cast<uint32_t*>(&h);
                }
#pragma unroll
                for (int tn8 = 0; tn8 < 4; tn8++) {
                    const uint32_t* bm = &wm[(tn8 >> 1) * 4 + (tn8 & 1) * 2];
                    const uint32_t* bv = &wv[(tn8 >> 1) * 4 + (tn8 & 1) * 2];
                    mma16816(accm[tm][tn8], xf, bm);
                    mma16816(accv[tm][tn8], xs, bv);
                }
            }
        };

        if (rot) { do_kk(2); do_kk(3); do_kk(0); do_kk(1); }
        else     { do_kk(0); do_kk(1); do_kk(2); do_kk(3); }

        // this warp is done reading stage cons_stage
        if (lane == 0) MBARRIER_ARRIVE(sb + SM_EMPTY + cons_stage * 8);
        if (++cons_stage == 4) { cons_stage = 0; cons_phase ^= 1; }

        // ---- produce chunk i+3 ----
        if (i + 3 < NCHUNK) {
            MBARRIER_WAIT_RLX(sb + SM_EMPTY + prod_stage * 8, prod_phase);
            load_chunk(i + 3, prod_stage);
            if (++prod_stage == 4) { prod_stage = 0; prod_phase ^= 1; }
        }
    }

    // ---------------- epilogue ----------------
    int ob = o0 + warp_n * 32 + 2 * (lane & 3);
    float2 bm2[4], bv2[4];
#pragma unroll
    for (int tn8 = 0; tn8 < 4; tn8++) {
        bm2[tn8] = *reinterpret_cast<const float2*>(&g_b_mean[ob + tn8 * 8]);
        bv2[tn8] = *reinterpret_cast<const float2*>(&g_b_var[ob + tn8 * 8]);
    }
    int mrow = m0 + warp_m * 64 + (lane >> 2);
#pragma unroll
    for (int tm = 0; tm < 4; tm++) {
        size_t r0 = (size_t)(mrow + tm * 16) * (2 * ODIM);
        size_t r8 = (size_t)(mrow + tm * 16 + 8) * (2 * ODIM);
#pragma unroll
        for (int tn8 = 0; tn8 < 4; tn8++) {
            int oc = ob + tn8 * 8;
            float2 v;
            v.x = accm[tm][tn8][0] + bm2[tn8].x;
            v.y = accm[tm][tn8][1] + bm2[tn8].y;
            *reinterpret_cast<float2*>(out + r0 + oc) = v;
            v.x = accm[tm][tn8][2] + bm2[tn8].x;
            v.y = accm[tm][tn8][3] + bm2[tn8].y;
            *reinterpret_cast<float2*>(out + r8 + oc) = v;
            v.x = accv[tm][tn8][0] + bv2[tn8].x;
            v.y = accv[tm][tn8][1] + bv2[tn8].y;
            *reinterpret_cast<float2*>(out + r0 + ODIM + oc) = v;
            v.x = accv[tm][tn8][2] + bv2[tn8].x;
            v.y = accv[tm][tn8][3] + bv2[tn8].y;
            *reinterpret_cast<float2*>(out + r8 + ODIM + oc) = v;
        }
    }
}

// ---------------- launch -----------------------------------------------------------
extern "C" void kernel_launch(void* const* d_in, const int* in_sizes, int n_in,
                              void* d_out, int out_size) {
    (void)in_sizes; (void)n_in; (void)out_size;
    const float* x  = (const float*)d_in[0];
    const float* Wl = (const float*)d_in[1];
    const float* bl = (const float*)d_in[2];
    float* out = (float*)d_out;

    prep_w_kernel<<<WELEMS / 4 / 256, 256>>>(Wl);   // 16384 blocks
    prep_x_kernel<<<XELEMS / 4 / 256, 256>>>(x);    // 8192 blocks
    prep_b_kernel<<<ODIM / 256, 256>>>(bl);         // 16 blocks

    cudaFuncSetAttribute(gemm_kernel, cudaFuncAttributeMaxDynamicSharedMemorySize, DYN_SMEM);
    gemm_kernel<<<dim3(NROWS / 128, ODIM / 128, 1), 256, DYN_SMEM>>>(out);
}